// round 3
// baseline (speedup 1.0000x reference)
#include <cuda_runtime.h>

#define H     4096
#define K     32
#define WO    4065          // H - K + 1
#define SW    128           // output cols per strip (per CTA)
#define RCH   224           // output rows per chunk
#define NT    128           // threads per CTA
#define BROWS 16            // rows per batch
#define CLD   159           // columns loaded per row: outputs 0..127 need cols 0..158
#define DP    168           // staging pitch; skc(158)=167 < 168, no row aliasing
#define RP    136           // ring pitch
#define RING  48            // ring rows (>= 32 + BROWS)

// skewed column index inside a row: c -> c + c/16  (lane stride 17 within 16-blocks)
__device__ __forceinline__ int skc(int c) { return c + (c >> 4); }

__global__ void __launch_bounds__(NT)
fused_box(const float* __restrict__ img,
          const float* __restrict__ som,
          const float* __restrict__ var,
          float* __restrict__ out)
{
    __shared__ float simg[K * K];          //  4 KB
    __shared__ float d[BROWS * DP];        // 10.5 KB  dist staging, skewed cols
    __shared__ float ring[RING * RP];      // 25.5 KB  horizontal box sums, skewed cols

    const int tid = threadIdx.x;
    const int x0  = blockIdx.x * SW;
    const int y0  = blockIdx.y * RCH;

    for (int i = tid; i < K * K; i += NT) simg[i] = img[i];
    __syncthreads();

    const int yend = min(y0 + RCH + K - 2, H - 1);   // inclusive last input row
    const int nIn  = yend - y0 + 1;

    const int cb = tid & 7;        // col block (16 cols each)
    const int rr = tid >> 3;       // row within batch
    const int xo = x0 + tid;       // this thread's output column (phase 3)

    float colsum = 0.f;

    for (int b = 0; b < nIn; b += BROWS) {
        const int rb = min(BROWS, nIn - b);

        // ---- phase 1: load som/var, compute variance-weighted dist into staging
        const int total = rb * CLD;
        for (int idx = tid; idx < total; idx += NT) {
            int lr  = idx / CLD;
            int col = idx - lr * CLD;             // 0..158
            int gy  = y0 + b + lr;
            int gx  = x0 + col;
            float v = 0.f;
            if (gx < H) {
                size_t o  = (size_t)gy * H + gx;
                float s   = som[o];
                float w   = var[o];
                float iv  = simg[((gy & 31) << 5) | (gx & 31)];
                float df  = iv - s;
                v = __fdividef(df * df, w + 1e-8f);
            }
            d[lr * DP + skc(col)] = v;
        }
        __syncthreads();

        // ---- phase 2: horizontal K-wide box sums (register sliding window)
        if (rr < rb) {
            const float* dr = d + rr * DP;
            float* rg = ring + ((b + rr) % RING) * RP;
            const int c0 = cb * 16;
            float s = 0.f;
#pragma unroll
            for (int i = 0; i < K; i++) s += dr[skc(c0 + i)];
            rg[skc(c0)] = s;
#pragma unroll
            for (int j = 1; j < 16; j++) {
                s += dr[skc(c0 + j + K - 1)] - dr[skc(c0 + j - 1)];
                rg[skc(c0 + j)] = s;
            }
        }
        __syncthreads();

        // ---- phase 3: vertical running sum, one output column per thread
        const int soff = skc(tid);
        for (int r = 0; r < rb; r++) {
            int i = b + r;                         // local input row index
            colsum += ring[(i % RING) * RP + soff];
            if (i >= K - 1) {
                int j = y0 + i - (K - 1);          // global output row
                if (xo < WO && j < WO)
                    out[(size_t)j * WO + xo] = colsum;
                colsum -= ring[((i - (K - 1)) % RING) * RP + soff];
            }
        }
        // no trailing sync needed: phase 3 reads ring rows <= b+rb-1; the next
        // iteration's phase-2 ring writes are ordered behind the phase-1 barrier.
    }
}

extern "C" void kernel_launch(void* const* d_in, const int* in_sizes, int n_in,
                              void* d_out, int out_size)
{
    const float* img = (const float*)d_in[0];   // [32,32]
    const float* som = (const float*)d_in[1];   // [4096,4096]
    const float* var = (const float*)d_in[2];   // [4096,4096]
    float*       out = (float*)d_out;           // [4065,4065]

    dim3 grid((H + SW - 1) / SW,                // 32 strips
              (WO + RCH - 1) / RCH);            // 19 row chunks
    fused_box<<<grid, NT>>>(img, som, var, out);
}

// round 4
// speedup vs baseline: 1.5520x; 1.5520x over previous
#include <cuda_runtime.h>

#define H     4096
#define K     32
#define WO    4065          // H - K + 1
#define SW    128           // output cols per strip
#define RCH   320           // output rows per chunk -> 13 chunks, 416 CTAs (1 wave @3/SM)
#define NT    256
#define BROWS 32            // rows per batch (= 1280 float4s = 5*NT exactly)
#define DP    168           // staging pitch; DP%32==8 -> conflict-free with skew
#define RP    136           // ring pitch;    RP%32==8
#define RING  64            // power of 2; live range 63 rows

__device__ __forceinline__ int skc(int c) { return c + (c >> 4); }

__global__ void __launch_bounds__(NT)
fused_box(const float* __restrict__ img,
          const float* __restrict__ som,
          const float* __restrict__ var,
          float* __restrict__ out)
{
    __shared__ float simg[K * K];          //  4 KB
    __shared__ float d[BROWS * DP];        // 21 KB   dist staging (skewed)
    __shared__ float ring[RING * RP];      // 34.8 KB horizontal box sums (skewed)

    const int tid = threadIdx.x;
    const int x0  = blockIdx.x * SW;
    const int y0  = blockIdx.y * RCH;

    for (int i = tid; i < K * K; i += NT) simg[i] = img[i];
    __syncthreads();

    const int yend = min(y0 + RCH + K - 2, H - 1);
    const int nIn  = yend - y0 + 1;

    const int cb = tid & 7;         // col block (16 cols)
    const int rr = tid >> 3;        // row within batch (0..31)
    const int soff = skc(tid & 127);
    const int xo   = x0 + tid;      // phase-3 column (tid < 128 only)

    float colsum = 0.f;

    for (int b = 0; b < nIn; b += BROWS) {
        const int rb = min(BROWS, nIn - b);
        const int total4 = rb * 40;               // float4s this batch

        // ---- phase 1: vectorized loads, variance-weighted dist -> staging
#pragma unroll
        for (int k = 0; k < 5; k++) {
            int idx = tid + k * NT;
            bool act = idx < total4;
            int lr  = idx / 40;
            int c4  = idx - lr * 40;              // 0..39 -> cols 4*c4..4*c4+3
            int gy  = y0 + b + lr;
            int gx  = x0 + c4 * 4;
            float4 s4 = make_float4(0.f, 0.f, 0.f, 0.f);
            float4 w4 = make_float4(1.f, 1.f, 1.f, 1.f);
            if (act && gx < H) {
                size_t o = (size_t)gy * H + gx;
                s4 = *(const float4*)(som + o);
                w4 = *(const float4*)(var + o);
            }
            if (act) {
                int ib = (gy & 31) << 5;
                float v0 = 0.f, v1 = 0.f, v2 = 0.f, v3 = 0.f;
                if (gx < H) {
                    float f0 = simg[ib | ((gx    ) & 31)] - s4.x;
                    float f1 = simg[ib | ((gx + 1) & 31)] - s4.y;
                    float f2 = simg[ib | ((gx + 2) & 31)] - s4.z;
                    float f3 = simg[ib | ((gx + 3) & 31)] - s4.w;
                    v0 = __fdividef(f0 * f0, w4.x + 1e-8f);
                    v1 = __fdividef(f1 * f1, w4.y + 1e-8f);
                    v2 = __fdividef(f2 * f2, w4.z + 1e-8f);
                    v3 = __fdividef(f3 * f3, w4.w + 1e-8f);
                }
                float* dr = d + lr * DP;
                int c = c4 * 4;
                dr[skc(c)]     = v0;
                dr[skc(c + 1)] = v1;
                dr[skc(c + 2)] = v2;
                if (c + 3 < 159) dr[skc(c + 3)] = v3;   // col 159 unused; skc(159)==DP aliases
            }
        }
        __syncthreads();

        // ---- phase 2: horizontal K-wide box sums (one (row, 16-col block) per thread)
        if (rr < rb) {
            const float* dr = d + rr * DP;
            float* rg = ring + ((b + rr) & (RING - 1)) * RP;
            const int c0 = cb * 16;
            float s = 0.f;
#pragma unroll
            for (int i = 0; i < K; i++) s += dr[skc(c0 + i)];
            rg[skc(c0)] = s;
#pragma unroll
            for (int j = 1; j < 16; j++) {
                s += dr[skc(c0 + j + K - 1)] - dr[skc(c0 + j - 1)];
                rg[skc(c0 + j)] = s;
            }
        }
        __syncthreads();

        // ---- phase 3: vertical running sum, one column per thread (tid < 128)
        if (tid < SW) {
#pragma unroll 4
            for (int r = 0; r < rb; r++) {
                int i = b + r;
                colsum += ring[(i & (RING - 1)) * RP + soff];
                if (i >= K - 1) {
                    int j = y0 + i - (K - 1);
                    if (xo < WO && j < WO)
                        out[(size_t)j * WO + xo] = colsum;
                    colsum -= ring[((i - (K - 1)) & (RING - 1)) * RP + soff];
                }
            }
        }
        // ordering: phase3 reads ring rows <= b+rb-1; next phase2's ring writes
        // (rows b+32..b+63 mod 64, which alias the oldest live rows) sit behind
        // the next phase-1 __syncthreads. Staging d reuse is likewise ordered.
    }
}

extern "C" void kernel_launch(void* const* d_in, const int* in_sizes, int n_in,
                              void* d_out, int out_size)
{
    const float* img = (const float*)d_in[0];   // [32,32]
    const float* som = (const float*)d_in[1];   // [4096,4096]
    const float* var = (const float*)d_in[2];   // [4096,4096]
    float*       out = (float*)d_out;           // [4065,4065]

    dim3 grid((H + SW - 1) / SW,                // 32 strips
              (WO + RCH - 1) / RCH);            // 13 row chunks -> 416 CTAs
    fused_box<<<grid, NT>>>(img, som, var, out);
}

// round 5
// speedup vs baseline: 2.3635x; 1.5229x over previous
#include <cuda_runtime.h>
#include <cuda_bf16.h>

#define H     4096
#define K     32
#define WO    4065
#define NWARP 8
#define SW    (NWARP * 32)   // 256 output cols per CTA
#define RCH   160            // output rows per chunk -> 26 chunks
#define NT    (NWARP * 32)

// 32-col window sum from per-column vertical sums held across the warp:
// lane l owns vsLo (col base+l) and vsHi (col base+32+l).
// out col base+l = sum_{j>=l} vsLo[j] + sum_{j<l} vsHi[j]
//                = totLo + exclusive_prefix_l(vsHi - vsLo)
__device__ __forceinline__ float window_sum(float vsLo, float vsHi, int lane)
{
    float w = vsHi - vsLo;
    float incl = w;
#pragma unroll
    for (int d = 1; d < 32; d <<= 1) {
        float t = __shfl_up_sync(0xffffffffu, incl, d);
        if (lane >= d) incl += t;
    }
    float tot = vsLo;
#pragma unroll
    for (int d = 16; d; d >>= 1)
        tot += __shfl_xor_sync(0xffffffffu, tot, d);
    return tot + incl - w;   // tot + exclusive prefix of w
}

__device__ __forceinline__ float2 row_dist(const float* __restrict__ som,
                                           const float* __restrict__ var,
                                           const float* __restrict__ simg,
                                           size_t o, int y, int lane, bool hiOk)
{
    float sLo = som[o];
    float wLo = var[o];
    float sHi = hiOk ? som[o + 32] : 0.f;
    float wHi = hiOk ? var[o + 32] : 1.f;
    float iv  = simg[((y & 31) << 5) + lane];   // img col == x&31 == lane (base%32==0)
    float fLo = iv - sLo, fHi = iv - sHi;
    float dLo = __fdividef(fLo * fLo, wLo + 1e-8f);
    float dHi = hiOk ? __fdividef(fHi * fHi, wHi + 1e-8f) : 0.f;
    return make_float2(dLo, dHi);
}

__global__ void __launch_bounds__(NT)
fused_warp(const float* __restrict__ img,
           const float* __restrict__ som,
           const float* __restrict__ var,
           float* __restrict__ out)
{
    __shared__ float simg[K * K];                    //  4 KB
    __shared__ __nv_bfloat162 ring[NWARP][K][32];    // 32 KB  warp-private dist history

    const int tid  = threadIdx.x;
    const int wid  = tid >> 5;
    const int lane = tid & 31;

    for (int i = tid; i < K * K; i += NT) simg[i] = img[i];
    __syncthreads();   // the only barrier

    const int  x     = blockIdx.x * SW + (wid << 5) + lane;
    const bool hiOk  = (x + 32 < H);
    const bool outOk = (x < WO);
    const int  j0    = blockIdx.y * RCH;
    const int  jend  = min(j0 + RCH, WO);   // exclusive
    const int  yend  = jend + K - 2;        // inclusive last input row (<= 4095)

    __nv_bfloat162* rslot = &ring[wid][0][lane];     // + 32*(y&31)

    float vsLo = 0.f, vsHi = 0.f;
    size_t o = (size_t)j0 * H + x;

    // ---- warmup: accumulate 32 rows (fills ring, builds first window)
#pragma unroll 4
    for (int y = j0; y < j0 + K; y++) {
        float2 dd = row_dist(som, var, simg, o, y, lane, hiOk);
        rslot[(y & 31) << 5] = __floats2bfloat162_rn(dd.x, dd.y);
        vsLo += dd.x;
        vsHi += dd.y;
        o += H;
    }

    // first output row (j = j0)
    {
        float res = window_sum(vsLo, vsHi, lane);
        if (outOk) out[(size_t)j0 * WO + x] = res;
    }

    // ---- main loop: slide the vertical window one row per iteration
    float* orow = out + (size_t)(j0 + 1) * WO + x;
#pragma unroll 2
    for (int y = j0 + K; y <= yend; y++) {
        float2 dd = row_dist(som, var, simg, o, y, lane, hiOk);
        const int slot = (y & 31) << 5;
        float2 od = __bfloat1622float2(rslot[slot]);   // dist from 32 rows ago
        rslot[slot] = __floats2bfloat162_rn(dd.x, dd.y);
        vsLo += dd.x - od.x;
        vsHi += dd.y - od.y;
        float res = window_sum(vsLo, vsHi, lane);
        if (outOk) *orow = res;
        orow += WO;
        o += H;
    }
}

extern "C" void kernel_launch(void* const* d_in, const int* in_sizes, int n_in,
                              void* d_out, int out_size)
{
    const float* img = (const float*)d_in[0];   // [32,32]
    const float* som = (const float*)d_in[1];   // [4096,4096]
    const float* var = (const float*)d_in[2];   // [4096,4096]
    float*       out = (float*)d_out;           // [4065,4065]

    dim3 grid((WO + SW - 1) / SW,               // 16 strips
              (WO + RCH - 1) / RCH);            // 26 row chunks -> 416 CTAs
    fused_warp<<<grid, NT>>>(img, som, var, out);
}